// round 15
// baseline (speedup 1.0000x reference)
#include <cuda_runtime.h>
#include <cuda_bf16.h>
#include <math.h>
#include <stdint.h>

#define NUM_C   100
#define CPAD    128
#define DIM     256
#define TEMPV   0.7f
#define EPSV    1e-8f
#define NROWS   8192

// smem tiles: padded row stride 264 bf16 = 528 bytes (conflict-free ldmatrix)
#define BSTRIDE 528
#define BH_SIZE (CPAD * BSTRIDE)       // 67584
#define AT_SIZE (64 * BSTRIDE)         // 33792 (per A hi/lo tile)
#define AS_OFF  (BH_SIZE + 2 * AT_SIZE)        // 135168: A fp32 staging
#define SMEM_DYN (AS_OFF + 65536)              // 200704

// ---------------- device scratch ----------------
__device__ float g_countf[CPAD];
__device__ __align__(16) __nv_bfloat16 g_pTh[CPAD * DIM];   // protoT (bf16)
__device__ int   g_arrive;
__device__ int   g_depart;

// ---------------- helpers ----------------
__device__ __forceinline__ uint32_t smem_u32(const void* p) {
    uint32_t a;
    asm("{ .reg .u64 t; cvta.to.shared.u64 t, %1; cvt.u32.u64 %0, t; }" : "=r"(a) : "l"(p));
    return a;
}
__device__ __forceinline__ int get_label(const void* lab, int i, int is64) {
    return is64 ? (int)((const long long*)lab)[i] : ((const int*)lab)[i];
}
__device__ __forceinline__ void split2(float2 v, uint32_t& h, uint32_t& l) {
    __nv_bfloat16 hx = __float2bfloat16(v.x), hy = __float2bfloat16(v.y);
    float rx = v.x - __bfloat162float(hx);
    float ry = v.y - __bfloat162float(hy);
    __nv_bfloat162 H, L;
    H.x = hx; H.y = hy;
    L.x = __float2bfloat16(rx); L.y = __float2bfloat16(ry);
    h = *(uint32_t*)&H;
    l = *(uint32_t*)&L;
}
__device__ __forceinline__ void mma_bf16(float* d, const uint32_t* a, const uint32_t* b) {
    asm volatile(
        "mma.sync.aligned.m16n8k16.row.col.f32.bf16.bf16.f32 "
        "{%0,%1,%2,%3}, {%4,%5,%6,%7}, {%8,%9}, {%0,%1,%2,%3};"
        : "+f"(d[0]), "+f"(d[1]), "+f"(d[2]), "+f"(d[3])
        : "r"(a[0]), "r"(a[1]), "r"(a[2]), "r"(a[3]), "r"(b[0]), "r"(b[1]));
}
#define LDSM4(r, a) \
    asm volatile("ldmatrix.sync.aligned.m8n8.x4.shared.b16 {%0,%1,%2,%3}, [%4];" \
        : "=r"((r)[0]), "=r"((r)[1]), "=r"((r)[2]), "=r"((r)[3]) : "r"(a))
#define CP_ASYNC16(smem, gptr) \
    asm volatile("cp.async.cg.shared.global [%0], [%1], 16;" :: "r"(smem), "l"(gptr) : "memory")
#define CP_COMMIT() asm volatile("cp.async.commit_group;" ::: "memory")
#define CP_WAIT0()  asm volatile("cp.async.wait_group 0;" ::: "memory")

// ================= fused kernel =================
// 128 CTAs x 1024 threads, all co-resident (1 CTA/SM).
__global__ void __launch_bounds__(1024, 1)
k_fused(const float* __restrict__ f, const void* __restrict__ lab, float* out, int n) {
    extern __shared__ char dsm[];   // [B 67584][Ah 33792][Al 33792][Astage 65536]
    __shared__ float red[32];
    __shared__ int   s_m;
    __shared__ float cnt_sh[CPAD];
    __shared__ float invfn_sh[64];
    __shared__ int   lab_sh[64];
    __shared__ float rs_part[512];
    __shared__ float dg_part[512];
    __shared__ float red_sh[2];

    int t = threadIdx.x, wid = t >> 5, lid = t & 31;
    int c = blockIdx.x;                         // class owned in phase 1
    int row0 = blockIdx.x * 64;                 // rows owned in phase 2
    uint32_t dsm_u = smem_u32(dsm);

    // ======== issue A-tile staging (64 rows fp32 -> smem) before anything ========
    {
        const char* fA = (const char*)(f + (size_t)row0 * DIM);
        #pragma unroll
        for (int it = 0; it < 4; it++) {
            int i = t + it * 1024;
            CP_ASYNC16(dsm_u + AS_OFF + (uint32_t)(i * 16), fA + i * 16);
        }
        CP_COMMIT();
    }

    // ======== PHASE 1: prototype for class c (overlaps A staging) ========
    const int* l32 = (const int*)lab;
    if (t == 0) s_m = 0;
    int fl = 0;
    for (int i = t; i < (n >> 1); i += 1024) fl |= l32[2 * i + 1];
    int is64 = (__syncthreads_or(fl) == 0);     // also publishes s_m=0
    if (c == 0 && t == 0) out[0] = 0.f;

    int*   list = (int*)dsm;                    // 8192 ints (reused B region)
    float* wacc = (float*)(dsm + 32768);        // 32 x 256 floats
    float* red4 = (float*)dsm;                  // 4 x 256 floats (after list is dead)

    for (int i = t; i < n; i += 1024) {
        int li = is64 ? (int)((const long long*)lab)[i] : l32[i];
        if (li == c) { int p = atomicAdd(&s_m, 1); list[p] = i; }
    }
    __syncthreads();
    int m = s_m;

    float s[8];
    #pragma unroll
    for (int i = 0; i < 8; i++) s[i] = 0.f;
    for (int j = wid; j < m; j += 64) {
        const float* fr = f + (size_t)list[j] * DIM;
        float4 va0 = ((const float4*)fr)[lid];
        float4 vb0 = ((const float4*)fr)[32 + lid];
        float4 va1 = make_float4(0.f, 0.f, 0.f, 0.f), vb1 = va1;
        int j2 = j + 32;
        if (j2 < m) {
            const float* fr1 = f + (size_t)list[j2] * DIM;
            va1 = ((const float4*)fr1)[lid];
            vb1 = ((const float4*)fr1)[32 + lid];
        }
        s[0] += va0.x + va1.x; s[1] += va0.y + va1.y;
        s[2] += va0.z + va1.z; s[3] += va0.w + va1.w;
        s[4] += vb0.x + vb1.x; s[5] += vb0.y + vb1.y;
        s[6] += vb0.z + vb1.z; s[7] += vb0.w + vb1.w;
    }
    __syncthreads();                            // list dead; safe to reuse as red4
    *(float4*)&wacc[wid * DIM + lid * 4]       = make_float4(s[0], s[1], s[2], s[3]);
    *(float4*)&wacc[wid * DIM + 128 + lid * 4] = make_float4(s[4], s[5], s[6], s[7]);
    __syncthreads();

    // 1024-thread reduction: quarter q sums warps q*8..q*8+7 for dim d
    {
        int q = t >> 8, d = t & 255;
        float part = 0.f;
        #pragma unroll
        for (int w = 0; w < 8; w++) part += wacc[(q * 8 + w) * DIM + d];
        red4[q * 256 + d] = part;
    }
    __syncthreads();

    float p = 0.f;
    if (t < DIM) {
        p = red4[t] + red4[256 + t] + red4[512 + t] + red4[768 + t];
        p /= fmaxf((float)m, 1.0f);
    }
    float pp = (t < DIM) ? p * p : 0.f;
    #pragma unroll
    for (int o = 16; o > 0; o >>= 1) pp += __shfl_xor_sync(0xffffffffu, pp, o);
    if (t < DIM && lid == 0) red[wid] = pp;
    __syncthreads();
    if (t < DIM) {
        float ssum = red[0] + red[1] + red[2] + red[3] +
                     red[4] + red[5] + red[6] + red[7];
        float nrm = fmaxf(sqrtf(ssum), EPSV);
        g_pTh[c * DIM + t] = __float2bfloat16(p / (nrm * TEMPV));
        if (t == 0) g_countf[c] = (float)m;
    }
    __syncthreads();
    if (t == 0)
        asm volatile("red.release.gpu.global.add.s32 [%0], 1;" :: "l"(&g_arrive) : "memory");

    // ======== PHASE 2a: convert A tile from smem staging ========
    CP_WAIT0();
    __syncthreads();
    {
        int arow = t >> 4, c4 = t & 15;
        const float4* fr = (const float4*)(dsm + AS_OFF + arow * 1024);
        float4 v[4];
        #pragma unroll
        for (int i = 0; i < 4; i++) v[i] = fr[c4 + 16 * i];
        float ss = 0.f;
        #pragma unroll
        for (int i = 0; i < 4; i++) {
            ss += v[i].x * v[i].x + v[i].y * v[i].y + v[i].z * v[i].z + v[i].w * v[i].w;
            uint32_t h0, l0, h1, l1;
            split2(make_float2(v[i].x, v[i].y), h0, l0);
            split2(make_float2(v[i].z, v[i].w), h1, l1);
            int off = arow * BSTRIDE + (c4 + 16 * i) * 8;
            *(uint2*)(dsm + BH_SIZE + off)           = make_uint2(h0, h1);
            *(uint2*)(dsm + BH_SIZE + AT_SIZE + off) = make_uint2(l0, l1);
        }
        #pragma unroll
        for (int o = 1; o <= 8; o <<= 1) ss += __shfl_xor_sync(0xffffffffu, ss, o);
        if ((lid & 15) == 0) invfn_sh[arow] = 1.0f / fmaxf(sqrtf(ss), EPSV);
    }
    if (t < 64) lab_sh[t] = get_label(lab, row0 + t, is64);

    // ======== global barrier (self-resetting) ========
    if (t == 0) {
        int v;
        do {
            asm volatile("ld.acquire.gpu.b32 %0, [%1];" : "=r"(v) : "l"(&g_arrive));
        } while (v < CPAD);
        int old = atomicAdd(&g_depart, 1);
        if (old == CPAD - 1) { atomicExch(&g_arrive, 0); atomicExch(&g_depart, 0); }
    }
    __syncthreads();

    // ======== PHASE 2b: B fill + pipelined GEMM + epilogue ========
    {
        const uint4* gh = (const uint4*)g_pTh;
        #pragma unroll
        for (int it = 0; it < 4; it++) {
            int idx = t + it * 1024;
            int r = idx >> 5, cc = idx & 31;
            CP_ASYNC16(dsm_u + (uint32_t)(r * BSTRIDE + cc * 16), gh + idx);
        }
        CP_COMMIT();
    }
    if (t < CPAD) cnt_sh[t] = g_countf[t];
    CP_WAIT0();
    __syncthreads();

    int g = lid >> 2, tq = lid & 3;
    int wtile = wid & 3, eig = wid >> 2;
    int m8 = lid >> 3, j8 = lid & 7;
    uint32_t laneA = (uint32_t)(((m8 & 1) * 8 + j8) * BSTRIDE + (m8 >> 1) * 16);
    uint32_t laneB = (uint32_t)(((m8 >> 1) * 8 + j8) * BSTRIDE + (m8 & 1) * 16);
    uint32_t Abase_h = dsm_u + BH_SIZE + (uint32_t)(wtile * 16 * BSTRIDE) + laneA;
    uint32_t Abase_l = Abase_h + AT_SIZE;
    uint32_t Bbase   = dsm_u + (uint32_t)(eig * 16 * BSTRIDE) + laneB;

    float acc0[4] = {0.f, 0.f, 0.f, 0.f};
    float acc1[4] = {0.f, 0.f, 0.f, 0.f};

    uint32_t ah[4], al[4], bh[4];
    LDSM4(ah, Abase_h);
    LDSM4(bh, Bbase);
    LDSM4(al, Abase_l);
    #pragma unroll
    for (int kt = 0; kt < 16; kt++) {
        uint32_t ah2[4], al2[4], bh2[4];
        if (kt < 15) {
            LDSM4(ah2, Abase_h + (kt + 1) * 32);
            LDSM4(bh2, Bbase   + (kt + 1) * 32);
            LDSM4(al2, Abase_l + (kt + 1) * 32);
        }
        mma_bf16(acc0, ah, bh);
        mma_bf16(acc1, ah, bh + 2);
        mma_bf16(acc0, al, bh);
        mma_bf16(acc1, al, bh + 2);
        #pragma unroll
        for (int q = 0; q < 4; q++) { ah[q] = ah2[q]; al[q] = al2[q]; bh[q] = bh2[q]; }
    }

    int wr0 = wtile * 16 + g;
    int chb = eig * 16;
    float ifn0 = invfn_sh[wr0], ifn1 = invfn_sh[wr0 + 8];
    int   lb0  = lab_sh[wr0],   lb1  = lab_sh[wr0 + 8];
    float rs0 = 0.f, rs1 = 0.f, dg0 = 0.f, dg1 = 0.f;
    #pragma unroll
    for (int nt = 0; nt < 2; nt++) {
        const float* a = nt ? acc1 : acc0;
        #pragma unroll
        for (int cc = 0; cc < 2; cc++) {
            int cls = chb + nt * 8 + 2 * tq + cc;
            float cw = cnt_sh[cls];
            float v0 = a[cc]     * ifn0;
            float v1 = a[2 + cc] * ifn1;
            rs0 += cw * __expf(v0);
            rs1 += cw * __expf(v1);
            if (cls == lb0) dg0 = v0;
            if (cls == lb1) dg1 = v1;
        }
    }
    #pragma unroll
    for (int o = 1; o <= 2; o <<= 1) {
        rs0 += __shfl_xor_sync(0xffffffffu, rs0, o);
        rs1 += __shfl_xor_sync(0xffffffffu, rs1, o);
        dg0 += __shfl_xor_sync(0xffffffffu, dg0, o);
        dg1 += __shfl_xor_sync(0xffffffffu, dg1, o);
    }
    if (tq == 0) {
        rs_part[eig * 64 + wr0]     = rs0;
        rs_part[eig * 64 + wr0 + 8] = rs1;
        dg_part[eig * 64 + wr0]     = dg0;
        dg_part[eig * 64 + wr0 + 8] = dg1;
    }
    __syncthreads();

    if (t < 64) {
        float rsum = 0.f, dsum = 0.f;
        #pragma unroll
        for (int e = 0; e < 8; e++) {
            rsum += rs_part[e * 64 + t];
            dsum += dg_part[e * 64 + t];
        }
        float lr = __logf(rsum) - dsum;
        #pragma unroll
        for (int o = 16; o > 0; o >>= 1) lr += __shfl_down_sync(0xffffffffu, lr, o);
        if (lid == 0) red_sh[wid] = lr;
    }
    __syncthreads();
    if (t == 0) atomicAdd(out, (red_sh[0] + red_sh[1]) / (float)n);
}

// ---------------- launch ----------------
extern "C" void kernel_launch(void* const* d_in, const int* in_sizes, int n_in,
                              void* d_out, int out_size) {
    const float* f = (const float*)d_in[0];
    const void*  lab = d_in[1];
    float* out = (float*)d_out;
    int n = in_sizes[1];   // 8192

    cudaFuncSetAttribute(k_fused, cudaFuncAttributeMaxDynamicSharedMemorySize, SMEM_DYN);
    k_fused<<<CPAD, 1024, SMEM_DYN>>>(f, lab, out, n);
}

// round 16
// speedup vs baseline: 1.0133x; 1.0133x over previous
#include <cuda_runtime.h>
#include <cuda_bf16.h>
#include <math.h>
#include <stdint.h>

#define NUM_C   100
#define CPAD    128
#define DIM     256
#define TEMPV   0.7f
#define EPSV    1e-8f
#define NROWS   8192

// smem tiles: padded row stride 264 bf16 = 528 bytes (conflict-free ldmatrix)
#define BSTRIDE 528
#define BH_SIZE (CPAD * BSTRIDE)       // 67584
#define AT_SIZE (64 * BSTRIDE)         // 33792 (per A hi/lo tile)
#define AS_OFF  (BH_SIZE + 2 * AT_SIZE)        // 135168: A fp32 staging
#define SMEM_DYN (AS_OFF + 65536)              // 200704
#define K1_SMEM 65536                          // [list 32KB][wacc 32KB]

// ---------------- device scratch ----------------
__device__ float g_countf[CPAD];
__device__ __align__(16) __nv_bfloat16 g_pTh[CPAD * DIM];   // protoT (bf16); rows >=100 stay 0

// ---------------- helpers ----------------
__device__ __forceinline__ uint32_t smem_u32(const void* p) {
    uint32_t a;
    asm("{ .reg .u64 t; cvta.to.shared.u64 t, %1; cvt.u32.u64 %0, t; }" : "=r"(a) : "l"(p));
    return a;
}
__device__ __forceinline__ int get_label(const void* lab, int i, int is64) {
    return is64 ? (int)((const long long*)lab)[i] : ((const int*)lab)[i];
}
__device__ __forceinline__ void split2(float2 v, uint32_t& h, uint32_t& l) {
    __nv_bfloat16 hx = __float2bfloat16(v.x), hy = __float2bfloat16(v.y);
    float rx = v.x - __bfloat162float(hx);
    float ry = v.y - __bfloat162float(hy);
    __nv_bfloat162 H, L;
    H.x = hx; H.y = hy;
    L.x = __float2bfloat16(rx); L.y = __float2bfloat16(ry);
    h = *(uint32_t*)&H;
    l = *(uint32_t*)&L;
}
__device__ __forceinline__ void mma_bf16(float* d, const uint32_t* a, const uint32_t* b) {
    asm volatile(
        "mma.sync.aligned.m16n8k16.row.col.f32.bf16.bf16.f32 "
        "{%0,%1,%2,%3}, {%4,%5,%6,%7}, {%8,%9}, {%0,%1,%2,%3};"
        : "+f"(d[0]), "+f"(d[1]), "+f"(d[2]), "+f"(d[3])
        : "r"(a[0]), "r"(a[1]), "r"(a[2]), "r"(a[3]), "r"(b[0]), "r"(b[1]));
}
#define LDSM4(r, a) \
    asm volatile("ldmatrix.sync.aligned.m8n8.x4.shared.b16 {%0,%1,%2,%3}, [%4];" \
        : "=r"((r)[0]), "=r"((r)[1]), "=r"((r)[2]), "=r"((r)[3]) : "r"(a))
#define CP_ASYNC16(smem, gptr) \
    asm volatile("cp.async.cg.shared.global [%0], [%1], 16;" :: "r"(smem), "l"(gptr) : "memory")
#define CP_COMMIT() asm volatile("cp.async.commit_group;" ::: "memory")
#define CP_WAIT0()  asm volatile("cp.async.wait_group 0;" ::: "memory")

// ================= K1: prototypes (100 CTAs x 1024 threads) =================
__global__ void __launch_bounds__(1024, 1)
k_protos(const float* __restrict__ f, const void* __restrict__ lab, int n, float* out) {
    extern __shared__ char psm[];               // [list 32KB][wacc 32KB]
    __shared__ float red[32];
    __shared__ int   s_m;

    int t = threadIdx.x, wid = t >> 5, lid = t & 31;
    int c = blockIdx.x;
    if (t == 0) {
        cudaTriggerProgrammaticLaunchCompletion();   // let k_main start its prologue early
        s_m = 0;
    }
    const int* l32 = (const int*)lab;
    int fl = 0;
    for (int i = t; i < (n >> 1); i += 1024) fl |= l32[2 * i + 1];
    int is64 = (__syncthreads_or(fl) == 0);     // also publishes s_m=0
    if (c == 0 && t == 0) out[0] = 0.f;

    int*   list = (int*)psm;
    float* wacc = (float*)(psm + 32768);        // 32 x 256 floats
    float* red4 = (float*)psm;                  // reuse after list dead

    for (int i = t; i < n; i += 1024) {
        int li = is64 ? (int)((const long long*)lab)[i] : l32[i];
        if (li == c) { int p = atomicAdd(&s_m, 1); list[p] = i; }
    }
    __syncthreads();
    int m = s_m;

    float s[8];
    #pragma unroll
    for (int i = 0; i < 8; i++) s[i] = 0.f;
    for (int j = wid; j < m; j += 64) {
        const float* fr = f + (size_t)list[j] * DIM;
        float4 va0 = ((const float4*)fr)[lid];
        float4 vb0 = ((const float4*)fr)[32 + lid];
        float4 va1 = make_float4(0.f, 0.f, 0.f, 0.f), vb1 = va1;
        int j2 = j + 32;
        if (j2 < m) {
            const float* fr1 = f + (size_t)list[j2] * DIM;
            va1 = ((const float4*)fr1)[lid];
            vb1 = ((const float4*)fr1)[32 + lid];
        }
        s[0] += va0.x + va1.x; s[1] += va0.y + va1.y;
        s[2] += va0.z + va1.z; s[3] += va0.w + va1.w;
        s[4] += vb0.x + vb1.x; s[5] += vb0.y + vb1.y;
        s[6] += vb0.z + vb1.z; s[7] += vb0.w + vb1.w;
    }
    __syncthreads();                            // list dead
    *(float4*)&wacc[wid * DIM + lid * 4]       = make_float4(s[0], s[1], s[2], s[3]);
    *(float4*)&wacc[wid * DIM + 128 + lid * 4] = make_float4(s[4], s[5], s[6], s[7]);
    __syncthreads();

    {   // 1024-thread quarter reduction
        int q = t >> 8, d = t & 255;
        float part = 0.f;
        #pragma unroll
        for (int w = 0; w < 8; w++) part += wacc[(q * 8 + w) * DIM + d];
        red4[q * 256 + d] = part;
    }
    __syncthreads();

    float p = 0.f;
    if (t < DIM) {
        p = red4[t] + red4[256 + t] + red4[512 + t] + red4[768 + t];
        p /= fmaxf((float)m, 1.0f);
    }
    float pp = (t < DIM) ? p * p : 0.f;
    #pragma unroll
    for (int o = 16; o > 0; o >>= 1) pp += __shfl_xor_sync(0xffffffffu, pp, o);
    if (t < DIM && lid == 0) red[wid] = pp;
    __syncthreads();
    if (t < DIM) {
        float ssum = red[0] + red[1] + red[2] + red[3] +
                     red[4] + red[5] + red[6] + red[7];
        float nrm = fmaxf(sqrtf(ssum), EPSV);
        g_pTh[c * DIM + t] = __float2bfloat16(p / (nrm * TEMPV));
        if (t == 0) g_countf[c] = (float)m;
    }
}

// ================= K2: GEMM + epilogue (128 CTAs x 1024 threads, PDL) =================
__global__ void __launch_bounds__(1024, 1)
k_main(const float* __restrict__ f, const void* __restrict__ lab, float* out, int n) {
    extern __shared__ char dsm[];   // [B 67584][Ah 33792][Al 33792][Astage 65536]
    __shared__ float cnt_sh[CPAD];
    __shared__ float invfn_sh[64];
    __shared__ int   lab_sh[64];
    __shared__ float rs_part[512];
    __shared__ float dg_part[512];
    __shared__ float red_sh[2];

    int t = threadIdx.x, wid = t >> 5, lid = t & 31;
    int row0 = blockIdx.x * 64;
    uint32_t dsm_u = smem_u32(dsm);

    // ---- independent prologue (overlaps k_protos via PDL) ----
    {
        const char* fA = (const char*)(f + (size_t)row0 * DIM);
        #pragma unroll
        for (int it = 0; it < 4; it++) {
            int i = t + it * 1024;
            CP_ASYNC16(dsm_u + AS_OFF + (uint32_t)(i * 16), fA + i * 16);
        }
        CP_COMMIT();
    }
    const int* l32 = (const int*)lab;
    int fl = 0;
    for (int i = t; i < (n >> 1); i += 1024) fl |= l32[2 * i + 1];
    int is64 = (__syncthreads_or(fl) == 0);
    if (t < 64) lab_sh[t] = get_label(lab, row0 + t, is64);

    CP_WAIT0();
    __syncthreads();
    {   // convert A tile fp32 -> bf16 hi/lo + exact row norms
        int arow = t >> 4, c4 = t & 15;
        const float4* fr = (const float4*)(dsm + AS_OFF + arow * 1024);
        float4 v[4];
        #pragma unroll
        for (int i = 0; i < 4; i++) v[i] = fr[c4 + 16 * i];
        float ss = 0.f;
        #pragma unroll
        for (int i = 0; i < 4; i++) {
            ss += v[i].x * v[i].x + v[i].y * v[i].y + v[i].z * v[i].z + v[i].w * v[i].w;
            uint32_t h0, l0, h1, l1;
            split2(make_float2(v[i].x, v[i].y), h0, l0);
            split2(make_float2(v[i].z, v[i].w), h1, l1);
            int off = arow * BSTRIDE + (c4 + 16 * i) * 8;
            *(uint2*)(dsm + BH_SIZE + off)           = make_uint2(h0, h1);
            *(uint2*)(dsm + BH_SIZE + AT_SIZE + off) = make_uint2(l0, l1);
        }
        #pragma unroll
        for (int o = 1; o <= 8; o <<= 1) ss += __shfl_xor_sync(0xffffffffu, ss, o);
        if ((lid & 15) == 0) invfn_sh[arow] = 1.0f / fmaxf(sqrtf(ss), EPSV);
    }

    // ---- wait for k_protos completion (HW grid dependency) ----
    cudaGridDependencySynchronize();

    // ---- B fill + GEMM + epilogue ----
    {
        const uint4* gh = (const uint4*)g_pTh;
        #pragma unroll
        for (int it = 0; it < 4; it++) {
            int idx = t + it * 1024;
            int r = idx >> 5, cc = idx & 31;
            CP_ASYNC16(dsm_u + (uint32_t)(r * BSTRIDE + cc * 16), gh + idx);
        }
        CP_COMMIT();
    }
    if (t < CPAD) cnt_sh[t] = g_countf[t];
    CP_WAIT0();
    __syncthreads();

    int g = lid >> 2, tq = lid & 3;
    int wtile = wid & 3, eig = wid >> 2;
    int m8 = lid >> 3, j8 = lid & 7;
    uint32_t laneA = (uint32_t)(((m8 & 1) * 8 + j8) * BSTRIDE + (m8 >> 1) * 16);
    uint32_t laneB = (uint32_t)(((m8 >> 1) * 8 + j8) * BSTRIDE + (m8 & 1) * 16);
    uint32_t Abase_h = dsm_u + BH_SIZE + (uint32_t)(wtile * 16 * BSTRIDE) + laneA;
    uint32_t Abase_l = Abase_h + AT_SIZE;
    uint32_t Bbase   = dsm_u + (uint32_t)(eig * 16 * BSTRIDE) + laneB;

    float acc0[4] = {0.f, 0.f, 0.f, 0.f};
    float acc1[4] = {0.f, 0.f, 0.f, 0.f};

    uint32_t ah[4], al[4], bh[4];
    LDSM4(ah, Abase_h);
    LDSM4(bh, Bbase);
    LDSM4(al, Abase_l);
    #pragma unroll
    for (int kt = 0; kt < 16; kt++) {
        uint32_t ah2[4], al2[4], bh2[4];
        if (kt < 15) {
            LDSM4(ah2, Abase_h + (kt + 1) * 32);
            LDSM4(bh2, Bbase   + (kt + 1) * 32);
            LDSM4(al2, Abase_l + (kt + 1) * 32);
        }
        mma_bf16(acc0, ah, bh);
        mma_bf16(acc1, ah, bh + 2);
        mma_bf16(acc0, al, bh);
        mma_bf16(acc1, al, bh + 2);
        #pragma unroll
        for (int q = 0; q < 4; q++) { ah[q] = ah2[q]; al[q] = al2[q]; bh[q] = bh2[q]; }
    }

    int wr0 = wtile * 16 + g;
    int chb = eig * 16;
    float ifn0 = invfn_sh[wr0], ifn1 = invfn_sh[wr0 + 8];
    int   lb0  = lab_sh[wr0],   lb1  = lab_sh[wr0 + 8];
    float rs0 = 0.f, rs1 = 0.f, dg0 = 0.f, dg1 = 0.f;
    #pragma unroll
    for (int nt = 0; nt < 2; nt++) {
        const float* a = nt ? acc1 : acc0;
        #pragma unroll
        for (int cc = 0; cc < 2; cc++) {
            int cls = chb + nt * 8 + 2 * tq + cc;
            float cw = cnt_sh[cls];
            float v0 = a[cc]     * ifn0;
            float v1 = a[2 + cc] * ifn1;
            rs0 += cw * __expf(v0);
            rs1 += cw * __expf(v1);
            if (cls == lb0) dg0 = v0;
            if (cls == lb1) dg1 = v1;
        }
    }
    #pragma unroll
    for (int o = 1; o <= 2; o <<= 1) {
        rs0 += __shfl_xor_sync(0xffffffffu, rs0, o);
        rs1 += __shfl_xor_sync(0xffffffffu, rs1, o);
        dg0 += __shfl_xor_sync(0xffffffffu, dg0, o);
        dg1 += __shfl_xor_sync(0xffffffffu, dg1, o);
    }
    if (tq == 0) {
        rs_part[eig * 64 + wr0]     = rs0;
        rs_part[eig * 64 + wr0 + 8] = rs1;
        dg_part[eig * 64 + wr0]     = dg0;
        dg_part[eig * 64 + wr0 + 8] = dg1;
    }
    __syncthreads();

    if (t < 64) {
        float rsum = 0.f, dsum = 0.f;
        #pragma unroll
        for (int e = 0; e < 8; e++) {
            rsum += rs_part[e * 64 + t];
            dsum += dg_part[e * 64 + t];
        }
        float lr = __logf(rsum) - dsum;
        #pragma unroll
        for (int o = 16; o > 0; o >>= 1) lr += __shfl_down_sync(0xffffffffu, lr, o);
        if (lid == 0) red_sh[wid] = lr;
    }
    __syncthreads();
    if (t == 0) atomicAdd(out, (red_sh[0] + red_sh[1]) / (float)n);
}

// ---------------- launch ----------------
extern "C" void kernel_launch(void* const* d_in, const int* in_sizes, int n_in,
                              void* d_out, int out_size) {
    const float* f = (const float*)d_in[0];
    const void*  lab = d_in[1];
    float* out = (float*)d_out;
    int n = in_sizes[1];   // 8192

    cudaFuncSetAttribute(k_protos, cudaFuncAttributeMaxDynamicSharedMemorySize, K1_SMEM);
    cudaFuncSetAttribute(k_main,   cudaFuncAttributeMaxDynamicSharedMemorySize, SMEM_DYN);

    // K1: plain launch
    k_protos<<<NUM_C, 1024, K1_SMEM>>>(f, lab, n, out);

    // K2: programmatic dependent launch — prologue overlaps K1
    cudaLaunchAttribute attrs[1];
    attrs[0].id = cudaLaunchAttributeProgrammaticStreamSerialization;
    attrs[0].val.programmaticStreamSerializationAllowed = 1;
    cudaLaunchConfig_t cfg = {};
    cfg.gridDim = dim3(CPAD, 1, 1);
    cfg.blockDim = dim3(1024, 1, 1);
    cfg.dynamicSmemBytes = SMEM_DYN;
    cfg.stream = 0;
    cfg.attrs = attrs;
    cfg.numAttrs = 1;
    cudaLaunchKernelEx(&cfg, k_main, f, lab, out, n);
}

// round 17
// speedup vs baseline: 1.1555x; 1.1404x over previous
#include <cuda_runtime.h>
#include <cuda_bf16.h>
#include <math.h>
#include <stdint.h>

#define NUM_C   100
#define CPAD    128
#define DIM     256
#define TEMPV   0.7f
#define EPSV    1e-8f
#define NROWS   8192

// smem tiles: padded row stride 264 bf16 = 528 bytes (conflict-free ldmatrix)
#define BSTRIDE 528
#define BH_SIZE (CPAD * BSTRIDE)       // 67584
#define AT_SIZE (64 * BSTRIDE)         // 33792 (A hi tile)
#define SMEM_DYN (BH_SIZE + AT_SIZE)   // 101376
#define K1_SMEM 65536                  // [list 32KB][wacc 32KB]

// ---------------- device scratch ----------------
__device__ float g_countf[CPAD];
__device__ __align__(16) __nv_bfloat16 g_pTh[CPAD * DIM];   // protoT (bf16); rows >=100 stay 0

// ---------------- helpers ----------------
__device__ __forceinline__ uint32_t smem_u32(const void* p) {
    uint32_t a;
    asm("{ .reg .u64 t; cvta.to.shared.u64 t, %1; cvt.u32.u64 %0, t; }" : "=r"(a) : "l"(p));
    return a;
}
__device__ __forceinline__ int get_label(const void* lab, int i, int is64) {
    return is64 ? (int)((const long long*)lab)[i] : ((const int*)lab)[i];
}
__device__ __forceinline__ uint32_t pack_bf16x2(float x, float y) {
    uint32_t r;
    asm("cvt.rn.bf16x2.f32 %0, %1, %2;" : "=r"(r) : "f"(y), "f"(x));
    return r;
}
__device__ __forceinline__ void mma_bf16(float* d, const uint32_t* a, const uint32_t* b) {
    asm volatile(
        "mma.sync.aligned.m16n8k16.row.col.f32.bf16.bf16.f32 "
        "{%0,%1,%2,%3}, {%4,%5,%6,%7}, {%8,%9}, {%0,%1,%2,%3};"
        : "+f"(d[0]), "+f"(d[1]), "+f"(d[2]), "+f"(d[3])
        : "r"(a[0]), "r"(a[1]), "r"(a[2]), "r"(a[3]), "r"(b[0]), "r"(b[1]));
}
#define LDSM4(r, a) \
    asm volatile("ldmatrix.sync.aligned.m8n8.x4.shared.b16 {%0,%1,%2,%3}, [%4];" \
        : "=r"((r)[0]), "=r"((r)[1]), "=r"((r)[2]), "=r"((r)[3]) : "r"(a))
#define CP_ASYNC16(smem, gptr) \
    asm volatile("cp.async.cg.shared.global [%0], [%1], 16;" :: "r"(smem), "l"(gptr) : "memory")
#define CP_COMMIT() asm volatile("cp.async.commit_group;" ::: "memory")
#define CP_WAIT0()  asm volatile("cp.async.wait_group 0;" ::: "memory")

// ================= K1: prototypes (100 CTAs x 1024 threads) =================
__global__ void __launch_bounds__(1024, 1)
k_protos(const float* __restrict__ f, const void* __restrict__ lab, int n, float* out) {
    extern __shared__ char psm[];               // [list 32KB][wacc 32KB]
    __shared__ float red[32];
    __shared__ int   s_m;

    int t = threadIdx.x, wid = t >> 5, lid = t & 31;
    int c = blockIdx.x;
    if (t == 0) {
        cudaTriggerProgrammaticLaunchCompletion();
        s_m = 0;
    }
    const int* l32 = (const int*)lab;
    int fl = 0;
    for (int i = t; i < (n >> 1); i += 1024) fl |= l32[2 * i + 1];
    int is64 = (__syncthreads_or(fl) == 0);     // also publishes s_m=0
    if (c == 0 && t == 0) out[0] = 0.f;

    int*   list = (int*)psm;
    float* wacc = (float*)(psm + 32768);        // 32 x 256 floats
    float* red4 = (float*)psm;                  // reuse after list dead

    for (int i = t; i < n; i += 1024) {
        int li = is64 ? (int)((const long long*)lab)[i] : l32[i];
        if (li == c) { int p = atomicAdd(&s_m, 1); list[p] = i; }
    }
    __syncthreads();
    int m = s_m;

    float s[8];
    #pragma unroll
    for (int i = 0; i < 8; i++) s[i] = 0.f;
    for (int j = wid; j < m; j += 64) {
        const float* fr = f + (size_t)list[j] * DIM;
        float4 va0 = ((const float4*)fr)[lid];
        float4 vb0 = ((const float4*)fr)[32 + lid];
        float4 va1 = make_float4(0.f, 0.f, 0.f, 0.f), vb1 = va1;
        int j2 = j + 32;
        if (j2 < m) {
            const float* fr1 = f + (size_t)list[j2] * DIM;
            va1 = ((const float4*)fr1)[lid];
            vb1 = ((const float4*)fr1)[32 + lid];
        }
        s[0] += va0.x + va1.x; s[1] += va0.y + va1.y;
        s[2] += va0.z + va1.z; s[3] += va0.w + va1.w;
        s[4] += vb0.x + vb1.x; s[5] += vb0.y + vb1.y;
        s[6] += vb0.z + vb1.z; s[7] += vb0.w + vb1.w;
    }
    __syncthreads();                            // list dead
    *(float4*)&wacc[wid * DIM + lid * 4]       = make_float4(s[0], s[1], s[2], s[3]);
    *(float4*)&wacc[wid * DIM + 128 + lid * 4] = make_float4(s[4], s[5], s[6], s[7]);
    __syncthreads();

    {   // 1024-thread quarter reduction
        int q = t >> 8, d = t & 255;
        float part = 0.f;
        #pragma unroll
        for (int w = 0; w < 8; w++) part += wacc[(q * 8 + w) * DIM + d];
        red4[q * 256 + d] = part;
    }
    __syncthreads();

    float p = 0.f;
    if (t < DIM) {
        p = red4[t] + red4[256 + t] + red4[512 + t] + red4[768 + t];
        p /= fmaxf((float)m, 1.0f);
    }
    float pp = (t < DIM) ? p * p : 0.f;
    #pragma unroll
    for (int o = 16; o > 0; o >>= 1) pp += __shfl_xor_sync(0xffffffffu, pp, o);
    if (t < DIM && lid == 0) red[wid] = pp;
    __syncthreads();
    if (t < DIM) {
        float ssum = red[0] + red[1] + red[2] + red[3] +
                     red[4] + red[5] + red[6] + red[7];
        float nrm = fmaxf(sqrtf(ssum), EPSV);
        g_pTh[c * DIM + t] = __float2bfloat16(p / (nrm * TEMPV));
        if (t == 0) g_countf[c] = (float)m;
    }
}

// ================= K2: bf16 HMMA GEMM + epilogue (128 CTAs x 1024 thr, PDL) =================
__global__ void __launch_bounds__(1024, 1)
k_main(const float* __restrict__ f, const void* __restrict__ lab, float* out, int n) {
    extern __shared__ char dsm[];               // [B 67584][Ah 33792]
    __shared__ float cnt_sh[CPAD];
    __shared__ float invfn_sh[64];
    __shared__ int   lab_sh[64];
    __shared__ float rs_part[512];
    __shared__ float dg_part[512];
    __shared__ float red_sh[2];

    int t = threadIdx.x, wid = t >> 5, lid = t & 31;
    int row0 = blockIdx.x * 64;
    uint32_t dsm_u = smem_u32(dsm);

    // ---- independent prologue (overlaps k_protos via PDL) ----
    const int* l32 = (const int*)lab;
    int fl = 0;
    for (int i = t; i < (n >> 1); i += 1024) fl |= l32[2 * i + 1];
    int is64 = (__syncthreads_or(fl) == 0);
    if (t < 64) lab_sh[t] = get_label(lab, row0 + t, is64);

    {   // A tile: gmem fp32 -> bf16 hi smem + exact row norms
        int arow = t >> 4, c4 = t & 15;
        const float4* fr = (const float4*)(f + (size_t)(row0 + arow) * DIM);
        float4 v[4];
        #pragma unroll
        for (int i = 0; i < 4; i++) v[i] = fr[c4 + 16 * i];
        float ss = 0.f;
        #pragma unroll
        for (int i = 0; i < 4; i++) {
            ss += v[i].x * v[i].x + v[i].y * v[i].y + v[i].z * v[i].z + v[i].w * v[i].w;
            uint32_t h0 = pack_bf16x2(v[i].x, v[i].y);
            uint32_t h1 = pack_bf16x2(v[i].z, v[i].w);
            *(uint2*)(dsm + BH_SIZE + arow * BSTRIDE + (c4 + 16 * i) * 8) = make_uint2(h0, h1);
        }
        #pragma unroll
        for (int o = 1; o <= 8; o <<= 1) ss += __shfl_xor_sync(0xffffffffu, ss, o);
        if ((lid & 15) == 0) invfn_sh[arow] = 1.0f / fmaxf(sqrtf(ss), EPSV);
    }

    // ---- wait for k_protos (HW grid dependency) ----
    cudaGridDependencySynchronize();

    // ---- B fill (cp.async) ----
    {
        const uint4* gh = (const uint4*)g_pTh;
        #pragma unroll
        for (int it = 0; it < 4; it++) {
            int idx = t + it * 1024;
            int r = idx >> 5, cc = idx & 31;
            CP_ASYNC16(dsm_u + (uint32_t)(r * BSTRIDE + cc * 16), gh + idx);
        }
        CP_COMMIT();
    }
    if (t < CPAD) cnt_sh[t] = g_countf[t];
    CP_WAIT0();
    __syncthreads();

    // ---- GEMM: warp w = row-tile (w&3)*16, class-eighth (w>>2)*16 ----
    int g = lid >> 2, tq = lid & 3;
    int wtile = wid & 3, eig = wid >> 2;
    int m8 = lid >> 3, j8 = lid & 7;
    uint32_t laneA = (uint32_t)(((m8 & 1) * 8 + j8) * BSTRIDE + (m8 >> 1) * 16);
    uint32_t laneB = (uint32_t)(((m8 >> 1) * 8 + j8) * BSTRIDE + (m8 & 1) * 16);
    uint32_t Abase = dsm_u + BH_SIZE + (uint32_t)(wtile * 16 * BSTRIDE) + laneA;
    uint32_t Bbase = dsm_u + (uint32_t)(eig * 16 * BSTRIDE) + laneB;

    float acc0[4] = {0.f, 0.f, 0.f, 0.f};
    float acc1[4] = {0.f, 0.f, 0.f, 0.f};

    // even/odd double-buffered pipeline — no register copies
    uint32_t aA[4], bA[4], aB[4], bB[4];
    LDSM4(aA, Abase);
    LDSM4(bA, Bbase);
    #pragma unroll
    for (int kt = 0; kt < 16; kt += 2) {
        LDSM4(aB, Abase + (kt + 1) * 32);
        LDSM4(bB, Bbase + (kt + 1) * 32);
        mma_bf16(acc0, aA, bA);
        mma_bf16(acc1, aA, bA + 2);
        if (kt < 14) {
            LDSM4(aA, Abase + (kt + 2) * 32);
            LDSM4(bA, Bbase + (kt + 2) * 32);
        }
        mma_bf16(acc0, aB, bB);
        mma_bf16(acc1, aB, bB + 2);
    }

    // ---- epilogue: partial row sums over this warp's 16 classes ----
    int wr0 = wtile * 16 + g;
    int chb = eig * 16;
    float ifn0 = invfn_sh[wr0], ifn1 = invfn_sh[wr0 + 8];
    int   lb0  = lab_sh[wr0],   lb1  = lab_sh[wr0 + 8];
    float rs0 = 0.f, rs1 = 0.f, dg0 = 0.f, dg1 = 0.f;
    #pragma unroll
    for (int nt = 0; nt < 2; nt++) {
        const float* a = nt ? acc1 : acc0;
        #pragma unroll
        for (int cc = 0; cc < 2; cc++) {
            int cls = chb + nt * 8 + 2 * tq + cc;
            float cw = cnt_sh[cls];
            float v0 = a[cc]     * ifn0;
            float v1 = a[2 + cc] * ifn1;
            rs0 += cw * __expf(v0);
            rs1 += cw * __expf(v1);
            if (cls == lb0) dg0 = v0;
            if (cls == lb1) dg1 = v1;
        }
    }
    #pragma unroll
    for (int o = 1; o <= 2; o <<= 1) {
        rs0 += __shfl_xor_sync(0xffffffffu, rs0, o);
        rs1 += __shfl_xor_sync(0xffffffffu, rs1, o);
        dg0 += __shfl_xor_sync(0xffffffffu, dg0, o);
        dg1 += __shfl_xor_sync(0xffffffffu, dg1, o);
    }
    if (tq == 0) {
        rs_part[eig * 64 + wr0]     = rs0;
        rs_part[eig * 64 + wr0 + 8] = rs1;
        dg_part[eig * 64 + wr0]     = dg0;
        dg_part[eig * 64 + wr0 + 8] = dg1;
    }
    __syncthreads();

    if (t < 64) {
        float rsum = 0.f, dsum = 0.f;
        #pragma unroll
        for (int e = 0; e < 8; e++) {
            rsum += rs_part[e * 64 + t];
            dsum += dg_part[e * 64 + t];
        }
        float lr = __logf(rsum) - dsum;
        #pragma unroll
        for (int o = 16; o > 0; o >>= 1) lr += __shfl_down_sync(0xffffffffu, lr, o);
        if (lid == 0) red_sh[wid] = lr;
    }
    __syncthreads();
    if (t == 0) atomicAdd(out, (red_sh[0] + red_sh[1]) / (float)n);
}

// ---------------- launch ----------------
extern "C" void kernel_launch(void* const* d_in, const int* in_sizes, int n_in,
                              void* d_out, int out_size) {
    const float* f = (const float*)d_in[0];
    const void*  lab = d_in[1];
    float* out = (float*)d_out;
    int n = in_sizes[1];   // 8192

    cudaFuncSetAttribute(k_protos, cudaFuncAttributeMaxDynamicSharedMemorySize, K1_SMEM);
    cudaFuncSetAttribute(k_main,   cudaFuncAttributeMaxDynamicSharedMemorySize, SMEM_DYN);

    k_protos<<<NUM_C, 1024, K1_SMEM>>>(f, lab, n, out);

    cudaLaunchAttribute attrs[1];
    attrs[0].id = cudaLaunchAttributeProgrammaticStreamSerialization;
    attrs[0].val.programmaticStreamSerializationAllowed = 1;
    cudaLaunchConfig_t cfg = {};
    cfg.gridDim = dim3(CPAD, 1, 1);
    cfg.blockDim = dim3(1024, 1, 1);
    cfg.dynamicSmemBytes = SMEM_DYN;
    cfg.stream = 0;
    cfg.attrs = attrs;
    cfg.numAttrs = 1;
    cudaLaunchKernelEx(&cfg, k_main, f, lab, out, n);
}